// round 14
// baseline (speedup 1.0000x reference)
#include <cuda_runtime.h>
#include <cuda_fp16.h>
#include <cstdint>
#include <math.h>

#define NMAX 50000
#define EMAX 400000
#define HID  256
#define LIN  196

// ---------------- scratch (device globals; no allocation allowed) -------------
__device__ float  g_xcur[NMAX * HID];
__device__ float  g_neigh[NMAX * HID];
__device__ __half g_h_hi[NMAX * HID];
__device__ __half g_h_lo[NMAX * HID];
__device__ __half g_xc_hi[NMAX * HID];
__device__ __half g_xc_lo[NMAX * HID];
__device__ __half g_ag_hi[NMAX * HID];
__device__ __half g_ag_lo[NMAX * HID];
__device__ __half g_w_hi[9 * HID * HID];
__device__ float  g_invdeg[NMAX];
__device__ int    g_cnt[NMAX];
__device__ int    g_rowptr[NMAX + 1];
__device__ int    g_esrc[EMAX];

// ---------------- helpers ------------------------------------------------------
__device__ __forceinline__ uint32_t smem_u32(const void* p) {
    uint32_t a;
    asm("{ .reg .u64 t; cvta.to.shared.u64 t, %1; cvt.u32.u64 %0, t; }" : "=r"(a) : "l"(p));
    return a;
}
__device__ __forceinline__ void cpa16(uint32_t dst, const void* src, int sz) {
    asm volatile("cp.async.ca.shared.global [%0], [%1], 16, %2;"
                 :: "r"(dst), "l"(src), "r"(sz) : "memory");
}
__device__ __forceinline__ void cpa_commit() {
    asm volatile("cp.async.commit_group;" ::: "memory");
}
__device__ __forceinline__ void cpa_wait0() {
    asm volatile("cp.async.wait_group 0;" ::: "memory");
}
__device__ __forceinline__ void cpa_wait1() {
    asm volatile("cp.async.wait_group 1;" ::: "memory");
}
__device__ __forceinline__ void mma16816(float* c, const uint32_t* a, const uint32_t* b) {
    asm volatile("mma.sync.aligned.m16n8k16.row.col.f32.f16.f16.f32 "
                 "{%0,%1,%2,%3}, {%4,%5,%6,%7}, {%8,%9}, {%0,%1,%2,%3};"
                 : "+f"(c[0]), "+f"(c[1]), "+f"(c[2]), "+f"(c[3])
                 : "r"(a[0]), "r"(a[1]), "r"(a[2]), "r"(a[3]), "r"(b[0]), "r"(b[1]));
}
__device__ __forceinline__ void ldsm_x4(uint32_t* r, uint32_t addr) {
    asm volatile("ldmatrix.sync.aligned.m8n8.x4.shared.b16 {%0,%1,%2,%3}, [%4];"
                 : "=r"(r[0]), "=r"(r[1]), "=r"(r[2]), "=r"(r[3]) : "r"(addr));
}
__device__ __forceinline__ void split2(float x, __half* hi, __half* lo) {
    __half h = __float2half_rn(x);
    *hi = h;
    *lo = __float2half_rn(x - __half2float(h));
}
__device__ __forceinline__ void split_store4(float4 v, __half2* hp, __half2* lp) {
    __half hx, hy, hz, hw, lx, ly, lz, lw;
    split2(v.x, &hx, &lx); split2(v.y, &hy, &ly);
    split2(v.z, &hz, &lz); split2(v.w, &hw, &lw);
    hp[0] = __halves2half2(hx, hy); hp[1] = __halves2half2(hz, hw);
    lp[0] = __halves2half2(lx, ly); lp[1] = __halves2half2(lz, lw);
}
__device__ __forceinline__ void add4(float4& a, float4 v) {
    a.x += v.x; a.y += v.y; a.z += v.z; a.w += v.w;
}

// ===== A-split (2-term) MMA GEMM: D = (Ah+Al) @ fp16(B)^T =====================
// 128x256 tile, 3-stage cp.async ring, 1 sync/iter.
#define BM 128
#define BN 256
#define BK 32
#define SA 40
#define O_ASH 0
#define O_ASL (128 * SA)
#define O_BSH (2 * 128 * SA)
#define BUF_H (O_BSH + 256 * SA)
#define HALVES_TOT (3 * BUF_H)
#define F_BIAS 0
#define F_LNG  256
#define F_LNB  512
#define F_MEAN 768
#define F_RSTD 896
#define F_RS   1024
#define F_RQ   1536
#define F_W2   256
#define F_B2   1536
#define F_HS   1544
#define FSCRATCH 4608
#define SMEM_BYTES (HALVES_TOT * 2 + FSCRATCH * 4)

__global__ void __launch_bounds__(512, 1)
mma_gemm(const __half* __restrict__ Ah1, const __half* __restrict__ Al1,
         const __half* __restrict__ Bh1,
         const __half* __restrict__ Ah2, const __half* __restrict__ Al2,
         const __half* __restrict__ Bh2,
         const float* __restrict__ bias, int M, int kIters, int mode,
         float* __restrict__ out1, __half* __restrict__ ohi, __half* __restrict__ olo,
         const float* __restrict__ lng, const float* __restrict__ lnb,
         const float* __restrict__ w2, const float* __restrict__ b2) {
    extern __shared__ char smem_raw[];
    float* fs = (float*)(smem_raw + HALVES_TOT * 2);
    uint32_t sb = smem_u32(smem_raw);

    int tid = threadIdx.x;
    int lane = tid & 31, wid = tid >> 5;
    int warpM = wid & 3, warpN = wid >> 2;
    int gid = lane >> 2, tig = lane & 3;
    int mbase = blockIdx.x * BM;

    for (int i = tid; i < 256; i += 512) fs[F_BIAS + i] = bias[i];
    if (mode == 1) {
        for (int i = tid; i < 256; i += 512) { fs[F_LNG + i] = lng[i]; fs[F_LNB + i] = lnb[i]; }
    } else if (mode == 3) {
        for (int i = tid; i < 1280; i += 512) fs[F_W2 + i] = w2[i];
        if (tid < 5) fs[F_B2 + tid] = b2[tid];
    }

    float acc[2][8][4];
#pragma unroll
    for (int a = 0; a < 2; a++)
#pragma unroll
        for (int b = 0; b < 8; b++)
#pragma unroll
            for (int c = 0; c < 4; c++) acc[a][b][c] = 0.f;

    int nA = Ah2 ? 2 : 1;
    int nIter = kIters * nA;

    int arow = tid >> 2, ac = tid & 3;
    int arg = mbase + arow;
    int asz = (arg < M) ? 16 : 0;
    int arclamp = (arg < M) ? arg : 0;

    int a_row_l = (lane & 15);
    int a_k_l   = (lane >> 4) * 8;
    int b_n_l   = ((lane >> 4) & 1) * 8 + (lane & 7);
    int b_k_l   = ((lane >> 3) & 1) * 8;

#define LOAD_TILE(IT)                                                                 \
    {                                                                                 \
        int ai_ = ((IT) >= kIters) ? 1 : 0;                                           \
        int kb_ = ((IT) - (ai_ ? kIters : 0)) * BK;                                   \
        uint32_t bs_ = (uint32_t)((IT) % 3) * BUF_H;                                  \
        const __half* Ah_ = ai_ ? Ah2 : Ah1;                                          \
        const __half* Al_ = ai_ ? Al2 : Al1;                                          \
        const __half* Bh_ = ai_ ? Bh2 : Bh1;                                          \
        uint32_t ad_ = sb + (bs_ + O_ASH + (uint32_t)(arow * SA + ac * 8)) * 2;       \
        cpa16(ad_, Ah_ + (size_t)arclamp * HID + kb_ + ac * 8, asz);                  \
        uint32_t ad2_ = sb + (bs_ + O_ASL + (uint32_t)(arow * SA + ac * 8)) * 2;      \
        cpa16(ad2_, Al_ + (size_t)arclamp * HID + kb_ + ac * 8, asz);                 \
        _Pragma("unroll")                                                             \
        for (int q_ = 0; q_ < 2; q_++) {                                              \
            int cid_ = tid + q_ * 512;                                                \
            int br_ = cid_ >> 2, bc_ = cid_ & 3;                                      \
            uint32_t bd_ = sb + (bs_ + O_BSH + (uint32_t)(br_ * SA + bc_ * 8)) * 2;   \
            cpa16(bd_, Bh_ + (size_t)br_ * HID + kb_ + bc_ * 8, 16);                  \
        }                                                                             \
    }

    LOAD_TILE(0);
    cpa_commit();
    if (nIter > 1) { LOAD_TILE(1); cpa_commit(); }

    for (int it = 0; it < nIter; it++) {
        if (it + 1 < nIter) cpa_wait1();
        else cpa_wait0();
        __syncthreads();
        uint32_t bufb = (uint32_t)(it % 3) * BUF_H;
        uint32_t ash = sb + (bufb + O_ASH) * 2;
        uint32_t asl = sb + (bufb + O_ASL) * 2;
        uint32_t bsh = sb + (bufb + O_BSH) * 2;
#pragma unroll
        for (int kk = 0; kk < 2; kk++) {
            int kof = kk * 16;
            uint32_t bh[8][2];
#pragma unroll
            for (int p = 0; p < 4; p++) {
                int n = warpN * 64 + p * 16 + b_n_l;
                uint32_t off = (uint32_t)(n * SA + kof + b_k_l) * 2;
                uint32_t r[4];
                ldsm_x4(r, bsh + off);
                bh[2 * p][0] = r[0]; bh[2 * p][1] = r[1];
                bh[2 * p + 1][0] = r[2]; bh[2 * p + 1][1] = r[3];
            }
#pragma unroll
            for (int mt = 0; mt < 2; mt++) {
                int row = warpM * 32 + mt * 16 + a_row_l;
                uint32_t off = (uint32_t)(row * SA + kof + a_k_l) * 2;
                uint32_t ah[4], al[4];
                ldsm_x4(ah, ash + off);
                ldsm_x4(al, asl + off);
#pragma unroll
                for (int nt = 0; nt < 8; nt++) {
                    mma16816(acc[mt][nt], ah, bh[nt]);
                    mma16816(acc[mt][nt], al, bh[nt]);
                }
            }
        }
        if (it + 2 < nIter) { LOAD_TILE(it + 2); cpa_commit(); }
    }
    __syncthreads();

    // ---------------- epilogue ---------------------------------------------------
    int colb = warpN * 64 + tig * 2;
    if (mode == 0) {
#pragma unroll
        for (int mt = 0; mt < 2; mt++)
#pragma unroll
            for (int up = 0; up < 2; up++) {
                int rnode = mbase + warpM * 32 + mt * 16 + gid + up * 8;
                if (rnode < M) {
#pragma unroll
                    for (int nt = 0; nt < 8; nt++) {
                        int col = colb + nt * 8;
                        float2 v = make_float2(acc[mt][nt][up * 2] + fs[F_BIAS + col],
                                               acc[mt][nt][up * 2 + 1] + fs[F_BIAS + col + 1]);
                        *(float2*)(out1 + (size_t)rnode * HID + col) = v;
                    }
                }
            }
    } else if (mode == 1) {
#pragma unroll
        for (int mt = 0; mt < 2; mt++)
#pragma unroll
            for (int up = 0; up < 2; up++) {
                float s = 0.f, q = 0.f;
#pragma unroll
                for (int nt = 0; nt < 8; nt++) {
                    int col = colb + nt * 8;
                    float v0 = fmaxf(acc[mt][nt][up * 2] + fs[F_BIAS + col], 0.f);
                    float v1 = fmaxf(acc[mt][nt][up * 2 + 1] + fs[F_BIAS + col + 1], 0.f);
                    s += v0 + v1; q += v0 * v0 + v1 * v1;
                }
                s += __shfl_xor_sync(0xffffffffu, s, 1); q += __shfl_xor_sync(0xffffffffu, q, 1);
                s += __shfl_xor_sync(0xffffffffu, s, 2); q += __shfl_xor_sync(0xffffffffu, q, 2);
                if (tig == 0) {
                    int rl = warpM * 32 + mt * 16 + gid + up * 8;
                    fs[F_RS + rl * 4 + warpN] = s;
                    fs[F_RQ + rl * 4 + warpN] = q;
                }
            }
        __syncthreads();
        if (tid < 128) {
            float s = fs[F_RS + tid * 4] + fs[F_RS + tid * 4 + 1] +
                      fs[F_RS + tid * 4 + 2] + fs[F_RS + tid * 4 + 3];
            float q = fs[F_RQ + tid * 4] + fs[F_RQ + tid * 4 + 1] +
                      fs[F_RQ + tid * 4 + 2] + fs[F_RQ + tid * 4 + 3];
            float mean = s * (1.f / 256.f);
            float var = q * (1.f / 256.f) - mean * mean;
            fs[F_MEAN + tid] = mean;
            fs[F_RSTD + tid] = rsqrtf(fmaxf(var, 0.f) + 1e-5f);
        }
        __syncthreads();
#pragma unroll
        for (int mt = 0; mt < 2; mt++)
#pragma unroll
            for (int up = 0; up < 2; up++) {
                int rl = warpM * 32 + mt * 16 + gid + up * 8;
                int rnode = mbase + rl;
                if (rnode >= M) continue;
                float mean = fs[F_MEAN + rl], rstd = fs[F_RSTD + rl];
#pragma unroll
                for (int nt = 0; nt < 8; nt++) {
                    int col = colb + nt * 8;
                    float v0 = fmaxf(acc[mt][nt][up * 2] + fs[F_BIAS + col], 0.f);
                    float v1 = fmaxf(acc[mt][nt][up * 2 + 1] + fs[F_BIAS + col + 1], 0.f);
                    float o0 = (v0 - mean) * rstd * fs[F_LNG + col] + fs[F_LNB + col];
                    float o1 = (v1 - mean) * rstd * fs[F_LNG + col + 1] + fs[F_LNB + col + 1];
                    *(float2*)(out1 + (size_t)rnode * HID + col) = make_float2(o0, o1);
                    __half h0, h1, l0, l1;
                    split2(o0, &h0, &l0); split2(o1, &h1, &l1);
                    *(__half2*)(ohi + (size_t)rnode * HID + col) = __halves2half2(h0, h1);
                    *(__half2*)(olo + (size_t)rnode * HID + col) = __halves2half2(l0, l1);
                }
            }
    } else if (mode == 2) {
#pragma unroll
        for (int mt = 0; mt < 2; mt++)
#pragma unroll
            for (int up = 0; up < 2; up++) {
                int rnode = mbase + warpM * 32 + mt * 16 + gid + up * 8;
                if (rnode >= M) continue;
#pragma unroll
                for (int nt = 0; nt < 8; nt++) {
                    int col = colb + nt * 8;
                    float v0 = acc[mt][nt][up * 2] + fs[F_BIAS + col];
                    float v1 = acc[mt][nt][up * 2 + 1] + fs[F_BIAS + col + 1];
                    *(float2*)(out1 + (size_t)rnode * HID + col) = make_float2(v0, v1);
                    float r0 = fmaxf(v0, 0.f), r1 = fmaxf(v1, 0.f);
                    __half h0, h1, l0, l1;
                    split2(r0, &h0, &l0); split2(r1, &h1, &l1);
                    *(__half2*)(ohi + (size_t)rnode * HID + col) = __halves2half2(h0, h1);
                    *(__half2*)(olo + (size_t)rnode * HID + col) = __halves2half2(l0, l1);
                }
            }
    } else {  // mode 3: post-MLP head
#pragma unroll
        for (int mt = 0; mt < 2; mt++)
#pragma unroll
            for (int up = 0; up < 2; up++) {
                float p[5] = {0.f, 0.f, 0.f, 0.f, 0.f};
#pragma unroll
                for (int nt = 0; nt < 8; nt++) {
                    int col = colb + nt * 8;
                    float v0 = acc[mt][nt][up * 2] + fs[F_BIAS + col];
                    float v1 = acc[mt][nt][up * 2 + 1] + fs[F_BIAS + col + 1];
#pragma unroll
                    for (int o = 0; o < 5; o++)
                        p[o] += v0 * fs[F_W2 + o * 256 + col] + v1 * fs[F_W2 + o * 256 + col + 1];
                }
#pragma unroll
                for (int o = 0; o < 5; o++) {
                    p[o] += __shfl_xor_sync(0xffffffffu, p[o], 1);
                    p[o] += __shfl_xor_sync(0xffffffffu, p[o], 2);
                }
                if (tig == 0) {
                    int rl = warpM * 32 + mt * 16 + gid + up * 8;
#pragma unroll
                    for (int o = 0; o < 5; o++)
                        fs[F_HS + (rl * 4 + warpN) * 5 + o] = p[o];
                }
            }
        __syncthreads();
        if (tid < 128) {
            float l[5];
#pragma unroll
            for (int o = 0; o < 5; o++)
                l[o] = fs[F_HS + (tid * 4 + 0) * 5 + o] + fs[F_HS + (tid * 4 + 1) * 5 + o] +
                       fs[F_HS + (tid * 4 + 2) * 5 + o] + fs[F_HS + (tid * 4 + 3) * 5 + o] +
                       fs[F_B2 + o];
            float m = fmaxf(fmaxf(fmaxf(l[0], l[1]), fmaxf(l[2], l[3])), l[4]);
            float ssum = expf(l[0] - m) + expf(l[1] - m) + expf(l[2] - m) +
                         expf(l[3] - m) + expf(l[4] - m);
            float L = m + logf(ssum);
            int node = mbase + tid;
            if (node < M) {
                float* op = out1 + (size_t)node * 5;
#pragma unroll
                for (int o = 0; o < 5; o++) op[o] = l[o] - L;
            }
        }
    }
}

// ---------------- all-weight conversion (9 matrices, one launch) ---------------
__global__ void convert_all_kernel(const float* __restrict__ w_self,
                                   const float* __restrict__ w_lin,
                                   const float* __restrict__ sage_wl,
                                   const float* __restrict__ sage_wr,
                                   const float* __restrict__ post_w1) {
    int widx = blockIdx.x >> 8;
    int row = blockIdx.x & 255;
    int col = threadIdx.x;
    const size_t WS = (size_t)HID * HID;
    const float* src;
    int Kreal;
    if (widx == 0)      { src = w_self;  Kreal = LIN; }
    else if (widx == 1) { src = w_lin;   Kreal = LIN; }
    else if (widx <= 4) { src = sage_wl + (size_t)(widx - 2) * WS; Kreal = HID; }
    else if (widx <= 7) { src = sage_wr + (size_t)(widx - 5) * WS; Kreal = HID; }
    else                { src = post_w1; Kreal = HID; }
    float v = (col < Kreal) ? src[(size_t)row * Kreal + col] : 0.f;
    g_w_hi[(size_t)widx * WS + (size_t)row * HID + col] = __float2half_rn(v);
}

// ---------------- conv 3x3 VALID + bias + relu -> hi/lo fp16 -------------------
__global__ void conv_relu_kernel(const float* __restrict__ x,
                                 const float* __restrict__ w,
                                 const float* __restrict__ b) {
    __shared__ float xs[324];
    __shared__ float ws[144];
    __shared__ float bs[4];
    int n = blockIdx.x;
    int t = threadIdx.x;
    const float* xp = x + (size_t)n * 324;
    for (int i = t; i < 324; i += 256) xs[i] = xp[i];
    if (t < 144) ws[t] = w[t];
    if (t < 4)   bs[t] = b[t];
    __syncthreads();
    __half hi = __float2half_rn(0.f), lo = hi;
    if (t < LIN) {
        int co = t / 49, r = t % 49, oi = r / 7, oj = r % 7;
        float s = bs[co];
#pragma unroll
        for (int ci = 0; ci < 4; ci++)
#pragma unroll
            for (int ki = 0; ki < 3; ki++)
#pragma unroll
                for (int kj = 0; kj < 3; kj++)
                    s += xs[ci * 81 + (oi + ki) * 9 + (oj + kj)] *
                         ws[((co * 4 + ci) * 3 + ki) * 3 + kj];
        s = fmaxf(s, 0.f);
        split2(s, &hi, &lo);
    }
    g_h_hi[(size_t)n * HID + t] = hi;
    g_h_lo[(size_t)n * HID + t] = lo;
}

// ---------------- CSR build ----------------------------------------------------
__global__ void zero_cnt_kernel(int Nn) {
    int i = blockIdx.x * blockDim.x + threadIdx.x;
    if (i < Nn) g_cnt[i] = 0;
}
__global__ void hist_kernel(const int* __restrict__ ei, int E) {
    int e = blockIdx.x * blockDim.x + threadIdx.x;
    if (e < E) atomicAdd(&g_cnt[ei[E + e]], 1);
}
__global__ void scan_kernel(int Nn) {
    __shared__ int sums[1024];
    int t = threadIdx.x;
    int chunk = (Nn + 1023) / 1024;
    int beg = t * chunk;
    int end = beg + chunk; if (end > Nn) end = Nn;
    int s = 0;
    for (int i = beg; i < end && i >= 0; i++) s += g_cnt[i];
    sums[t] = s;
    __syncthreads();
    for (int off = 1; off < 1024; off <<= 1) {
        int v = 0;
        if (t >= off) v = sums[t - off];
        __syncthreads();
        sums[t] += v;
        __syncthreads();
    }
    int run = sums[t] - s;
    for (int i = beg; i < end; i++) { g_rowptr[i] = run; run += g_cnt[i]; }
    if (t == 1023) g_rowptr[Nn] = sums[1023];
}
__global__ void cursor_invdeg_kernel(int Nn) {
    int i = blockIdx.x * blockDim.x + threadIdx.x;
    if (i < Nn) {
        int r0 = g_rowptr[i], r1 = g_rowptr[i + 1];
        g_cnt[i] = r0;
        int d = r1 - r0;
        g_invdeg[i] = d > 0 ? 1.0f / (float)d : 0.0f;
    }
}
__global__ void scatter_kernel(const int* __restrict__ ei, int E) {
    int e = blockIdx.x * blockDim.x + threadIdx.x;
    if (e < E) {
        int d = ei[E + e];
        int pos = atomicAdd(&g_cnt[d], 1);
        g_esrc[pos] = ei[e];
    }
}

// ---------------- aggregation (warp/node, 2-edge unrolled dual accumulators) ----
__global__ void agg_first_kernel(const float* __restrict__ neigh,
                                 float* __restrict__ xcur, int Nn) {
    int gw = (blockIdx.x * blockDim.x + threadIdx.x) >> 5;
    if (gw >= Nn) return;
    int lane = threadIdx.x & 31;
    int beg = g_rowptr[gw], end = g_rowptr[gw + 1];
    float4 a0 = make_float4(0, 0, 0, 0), a1 = a0;
    float4 b0 = a0, b1 = a0;
    int e = beg;
    for (; e + 1 < end; e += 2) {
        int s0 = g_esrc[e];
        int s1 = g_esrc[e + 1];
        const float4* p0 = (const float4*)(neigh + (size_t)s0 * HID);
        const float4* p1 = (const float4*)(neigh + (size_t)s1 * HID);
        float4 v00 = p0[lane], v01 = p0[lane + 32];
        float4 v10 = p1[lane], v11 = p1[lane + 32];
        if (s0 != gw) { add4(a0, v00); add4(a1, v01); }
        if (s1 != gw) { add4(b0, v10); add4(b1, v11); }
    }
    if (e < end) {
        int s0 = g_esrc[e];
        if (s0 != gw) {
            const float4* p0 = (const float4*)(neigh + (size_t)s0 * HID);
            add4(a0, p0[lane]); add4(a1, p0[lane + 32]);
        }
    }
    add4(a0, b0); add4(a1, b1);
    float4* q = (float4*)(xcur + (size_t)gw * HID);
    float4 c0 = q[lane], c1 = q[lane + 32];
    add4(c0, a0); add4(c1, a1);
    q[lane] = c0; q[lane + 32] = c1;
    __half2* hh = (__half2*)(g_xc_hi + (size_t)gw * HID);
    __half2* ll = (__half2*)(g_xc_lo + (size_t)gw * HID);
    split_store4(c0, hh + lane * 2, ll + lane * 2);
    split_store4(c1, hh + 64 + lane * 2, ll + 64 + lane * 2);
}
__global__ void agg_mean_kernel(const float* __restrict__ xcur, int Nn) {
    int gw = (blockIdx.x * blockDim.x + threadIdx.x) >> 5;
    if (gw >= Nn) return;
    int lane = threadIdx.x & 31;
    int beg = g_rowptr[gw], end = g_rowptr[gw + 1];
    float4 a0 = make_float4(0, 0, 0, 0), a1 = a0;
    float4 b0 = a0, b1 = a0;
    int e = beg;
    for (; e + 1 < end; e += 2) {
        int s0 = g_esrc[e];
        int s1 = g_esrc[e + 1];
        const float4* p0 = (const float4*)(xcur + (size_t)s0 * HID);
        const float4* p1 = (const float4*)(xcur + (size_t)s1 * HID);
        float4 v00 = p0[lane], v01 = p0[lane + 32];
        float4 v10 = p1[lane], v11 = p1[lane + 32];
        add4(a0, v00); add4(a1, v01);
        add4(b0, v10); add4(b1, v11);
    }
    if (e < end) {
        int s0 = g_esrc[e];
        const float4* p0 = (const float4*)(xcur + (size_t)s0 * HID);
        add4(a0, p0[lane]); add4(a1, p0[lane + 32]);
    }
    add4(a0, b0); add4(a1, b1);
    float sc = g_invdeg[gw];
    a0.x *= sc; a0.y *= sc; a0.z *= sc; a0.w *= sc;
    a1.x *= sc; a1.y *= sc; a1.z *= sc; a1.w *= sc;
    __half2* hh = (__half2*)(g_ag_hi + (size_t)gw * HID);
    __half2* ll = (__half2*)(g_ag_lo + (size_t)gw * HID);
    split_store4(a0, hh + lane * 2, ll + lane * 2);
    split_store4(a1, hh + 64 + lane * 2, ll + 64 + lane * 2);
}

// ---------------- launch -------------------------------------------------------
extern "C" void kernel_launch(void* const* d_in, const int* in_sizes, int n_in,
                              void* d_out, int out_size) {
    const float* x       = (const float*)d_in[0];
    const int*   ei      = (const int*)d_in[1];
    const float* conv_w  = (const float*)d_in[2];
    const float* conv_b  = (const float*)d_in[3];
    const float* w_self  = (const float*)d_in[4];
    const float* b_self  = (const float*)d_in[5];
    const float* w_lin   = (const float*)d_in[6];
    const float* b_lin   = (const float*)d_in[7];
    const float* sage_wl = (const float*)d_in[8];
    const float* sage_bl = (const float*)d_in[9];
    const float* sage_wr = (const float*)d_in[10];
    const float* ln_g    = (const float*)d_in[11];
    const float* ln_b    = (const float*)d_in[12];
    const float* post_w1 = (const float*)d_in[13];
    const float* post_b1 = (const float*)d_in[14];
    const float* post_w2 = (const float*)d_in[15];
    const float* post_b2 = (const float*)d_in[16];

    int N = in_sizes[0] / 324;
    int E = in_sizes[1] / 2;

    float* outp = (float*)d_out;
    float* emb  = outp;
    float* logp = outp + (size_t)N * HID;

    float *xcur, *neigh;
    __half *h_hi, *h_lo, *xc_hi, *xc_lo, *ag_hi, *ag_lo, *w_hi;
    cudaGetSymbolAddress((void**)&xcur,  g_xcur);
    cudaGetSymbolAddress((void**)&neigh, g_neigh);
    cudaGetSymbolAddress((void**)&h_hi,  g_h_hi);
    cudaGetSymbolAddress((void**)&h_lo,  g_h_lo);
    cudaGetSymbolAddress((void**)&xc_hi, g_xc_hi);
    cudaGetSymbolAddress((void**)&xc_lo, g_xc_lo);
    cudaGetSymbolAddress((void**)&ag_hi, g_ag_hi);
    cudaGetSymbolAddress((void**)&ag_lo, g_ag_lo);
    cudaGetSymbolAddress((void**)&w_hi,  g_w_hi);

    cudaFuncSetAttribute(mma_gemm,
                         cudaFuncAttributeMaxDynamicSharedMemorySize, SMEM_BYTES);

    const size_t WS = (size_t)HID * HID;
    int gTiles = (N + BM - 1) / BM;

    // #1: weight conversion
    convert_all_kernel<<<9 * 256, 256>>>(w_self, w_lin, sage_wl, sage_wr, post_w1);
    // #2: conv + relu -> h hi/lo
    conv_relu_kernel<<<N, 256>>>(x, conv_w, conv_b);
    // #3: zero histogram
    zero_cnt_kernel<<<(N + 255) / 256, 256>>>(N);
    // #4: GEMM: self_x -> xcur f32
    mma_gemm<<<gTiles, 512, SMEM_BYTES>>>(h_hi, h_lo, w_hi + 0 * WS,
                                          nullptr, nullptr, nullptr,
                                          b_self, N, 7, 0, xcur, nullptr, nullptr,
                                          nullptr, nullptr, nullptr, nullptr);
    // #5: histogram
    hist_kernel<<<(E + 255) / 256, 256>>>(ei, E);
    // #6: GEMM: neigh -> f32
    mma_gemm<<<gTiles, 512, SMEM_BYTES>>>(h_hi, h_lo, w_hi + 1 * WS,
                                          nullptr, nullptr, nullptr,
                                          b_lin, N, 7, 0, neigh, nullptr, nullptr,
                                          nullptr, nullptr, nullptr, nullptr);
    // #7-#9: CSR scan + cursors + scatter
    scan_kernel<<<1, 1024>>>(N);
    cursor_invdeg_kernel<<<(N + 255) / 256, 256>>>(N);
    scatter_kernel<<<(E + 255) / 256, 256>>>(ei, E);

    // #10: first-layer scatter-add -> xcur f32 + xc hi/lo
    int aggBlocks = (N + 7) / 8;
    agg_first_kernel<<<aggBlocks, 256>>>(neigh, xcur, N);

    // SAGE x3
    for (int i = 0; i < 3; i++) {
        agg_mean_kernel<<<aggBlocks, 256>>>(xcur, N);
        const __half* wlh = w_hi + (size_t)(2 + i) * WS;
        const __half* wrh = w_hi + (size_t)(5 + i) * WS;
        const float* bl = sage_bl + (size_t)i * HID;
        if (i < 2) {
            mma_gemm<<<gTiles, 512, SMEM_BYTES>>>(ag_hi, ag_lo, wlh,
                                                  xc_hi, xc_lo, wrh,
                                                  bl, N, 8, 1, xcur, xc_hi, xc_lo,
                                                  ln_g + (size_t)i * HID,
                                                  ln_b + (size_t)i * HID,
                                                  nullptr, nullptr);
        } else {
            mma_gemm<<<gTiles, 512, SMEM_BYTES>>>(ag_hi, ag_lo, wlh,
                                                  xc_hi, xc_lo, wrh,
                                                  bl, N, 8, 2, emb, xc_hi, xc_lo,
                                                  nullptr, nullptr, nullptr, nullptr);
        }
    }

    // post-MLP + head fused
    mma_gemm<<<gTiles, 512, SMEM_BYTES>>>(xc_hi, xc_lo, w_hi + 8 * WS,
                                          nullptr, nullptr, nullptr,
                                          post_b1, N, 8, 3, logp, nullptr, nullptr,
                                          nullptr, nullptr, post_w2, post_b2);
}

// round 16
// speedup vs baseline: 1.0530x; 1.0530x over previous
#include <cuda_runtime.h>
#include <cuda_fp16.h>
#include <cstdint>
#include <math.h>

#define NMAX 50000
#define EMAX 400000
#define HID  256
#define LIN  196

// ---------------- scratch (device globals; no allocation allowed) -------------
__device__ float  g_xcur[NMAX * HID];
__device__ float  g_neigh[NMAX * HID];
__device__ __half g_h_hi[NMAX * HID];
__device__ __half g_h_lo[NMAX * HID];
__device__ __half g_xc_hi[NMAX * HID];
__device__ __half g_xc_lo[NMAX * HID];
__device__ __half g_ag_hi[NMAX * HID];
__device__ __half g_ag_lo[NMAX * HID];
__device__ __half g_w_hi[9 * HID * HID];
__device__ float  g_invdeg[NMAX];
__device__ int    g_cnt[NMAX];
__device__ int    g_rowptr[NMAX + 1];
__device__ int    g_esrc[EMAX];

// ---------------- helpers ------------------------------------------------------
__device__ __forceinline__ uint32_t smem_u32(const void* p) {
    uint32_t a;
    asm("{ .reg .u64 t; cvta.to.shared.u64 t, %1; cvt.u32.u64 %0, t; }" : "=r"(a) : "l"(p));
    return a;
}
__device__ __forceinline__ void cpa16(uint32_t dst, const void* src, int sz) {
    asm volatile("cp.async.ca.shared.global [%0], [%1], 16, %2;"
                 :: "r"(dst), "l"(src), "r"(sz) : "memory");
}
__device__ __forceinline__ void cpa_commit() {
    asm volatile("cp.async.commit_group;" ::: "memory");
}
__device__ __forceinline__ void cpa_wait0() {
    asm volatile("cp.async.wait_group 0;" ::: "memory");
}
__device__ __forceinline__ void mma16816(float* c, const uint32_t* a, const uint32_t* b) {
    asm volatile("mma.sync.aligned.m16n8k16.row.col.f32.f16.f16.f32 "
                 "{%0,%1,%2,%3}, {%4,%5,%6,%7}, {%8,%9}, {%0,%1,%2,%3};"
                 : "+f"(c[0]), "+f"(c[1]), "+f"(c[2]), "+f"(c[3])
                 : "r"(a[0]), "r"(a[1]), "r"(a[2]), "r"(a[3]), "r"(b[0]), "r"(b[1]));
}
__device__ __forceinline__ void ldsm_x4(uint32_t* r, uint32_t addr) {
    asm volatile("ldmatrix.sync.aligned.m8n8.x4.shared.b16 {%0,%1,%2,%3}, [%4];"
                 : "=r"(r[0]), "=r"(r[1]), "=r"(r[2]), "=r"(r[3]) : "r"(addr));
}
__device__ __forceinline__ void split2(float x, __half* hi, __half* lo) {
    __half h = __float2half_rn(x);
    *hi = h;
    *lo = __float2half_rn(x - __half2float(h));
}
__device__ __forceinline__ void split_store4(float4 v, __half2* hp, __half2* lp) {
    __half hx, hy, hz, hw, lx, ly, lz, lw;
    split2(v.x, &hx, &lx); split2(v.y, &hy, &ly);
    split2(v.z, &hz, &lz); split2(v.w, &hw, &lw);
    hp[0] = __halves2half2(hx, hy); hp[1] = __halves2half2(hz, hw);
    lp[0] = __halves2half2(lx, ly); lp[1] = __halves2half2(lz, lw);
}

// ===== A-split (2-term) MMA GEMM: D = (Ah+Al) @ fp16(B)^T =====================
// 128x256 tile, BK=64, 2-stage ring, 1 sync/iter, 4 iters per K=256.
#define BM 128
#define BN 256
#define BK 64
#define SA 72                        // 144B rows: 16B-aligned, LDSM banks 4i conflict-free
#define O_ASH 0
#define O_ASL (128 * SA)             // 9216
#define O_BSH (2 * 128 * SA)         // 18432
#define BUF_H (O_BSH + 256 * SA)     // 36864 halves per stage (73728 B)
#define HALVES_TOT (2 * BUF_H)       // 73728 halves = 147456 B
#define F_BIAS 0
#define F_LNG  256
#define F_LNB  512
#define F_MEAN 768
#define F_RSTD 896
#define F_RS   1024
#define F_RQ   1536
#define F_W2   256
#define F_B2   1536
#define F_HS   1544
#define FSCRATCH 4608
#define SMEM_BYTES (HALVES_TOT * 2 + FSCRATCH * 4)   // 165888 B

__global__ void __launch_bounds__(512, 1)
mma_gemm(const __half* __restrict__ Ah1, const __half* __restrict__ Al1,
         const __half* __restrict__ Bh1,
         const __half* __restrict__ Ah2, const __half* __restrict__ Al2,
         const __half* __restrict__ Bh2,
         const float* __restrict__ bias, int M, int kIters, int mode,
         float* __restrict__ out1, __half* __restrict__ ohi, __half* __restrict__ olo,
         const float* __restrict__ lng, const float* __restrict__ lnb,
         const float* __restrict__ w2, const float* __restrict__ b2) {
    extern __shared__ char smem_raw[];
    float* fs = (float*)(smem_raw + HALVES_TOT * 2);
    uint32_t sb = smem_u32(smem_raw);

    int tid = threadIdx.x;
    int lane = tid & 31, wid = tid >> 5;
    int warpM = wid & 3, warpN = wid >> 2;
    int gid = lane >> 2, tig = lane & 3;
    int mbase = blockIdx.x * BM;

    for (int i = tid; i < 256; i += 512) fs[F_BIAS + i] = bias[i];
    if (mode == 1) {
        for (int i = tid; i < 256; i += 512) { fs[F_LNG + i] = lng[i]; fs[F_LNB + i] = lnb[i]; }
    } else if (mode == 3) {
        for (int i = tid; i < 1280; i += 512) fs[F_W2 + i] = w2[i];
        if (tid < 5) fs[F_B2 + tid] = b2[tid];
    }

    float acc[2][8][4];
#pragma unroll
    for (int a = 0; a < 2; a++)
#pragma unroll
        for (int b = 0; b < 8; b++)
#pragma unroll
            for (int c = 0; c < 4; c++) acc[a][b][c] = 0.f;

    int nA = Ah2 ? 2 : 1;
    int nIter = kIters * nA;

    // loader mapping: 8 threads/row, 8x16B chunks per 128B (64-half) row
    int lrow = tid >> 3, lc = tid & 7;
    int a_row_l = (lane & 15);
    int a_k_l   = (lane >> 4) * 8;
    int b_n_l   = ((lane >> 4) & 1) * 8 + (lane & 7);
    int b_k_l   = ((lane >> 3) & 1) * 8;

#define LOAD_TILE(IT)                                                                 \
    {                                                                                 \
        int ai_ = ((IT) >= kIters) ? 1 : 0;                                           \
        int kb_ = ((IT) - (ai_ ? kIters : 0)) * BK;                                   \
        uint32_t bs_ = (uint32_t)((IT) & 1) * BUF_H;                                  \
        const __half* Ah_ = ai_ ? Ah2 : Ah1;                                          \
        const __half* Al_ = ai_ ? Al2 : Al1;                                          \
        const __half* Bh_ = ai_ ? Bh2 : Bh1;                                          \
        _Pragma("unroll")                                                             \
        for (int q_ = 0; q_ < 2; q_++) {                                              \
            int row_ = lrow + q_ * 64;                                                \
            int node_ = mbase + row_;                                                 \
            int sz_ = (node_ < M) ? 16 : 0;                                           \
            int ncl_ = (node_ < M) ? node_ : 0;                                       \
            uint32_t doff_ = (bs_ + (uint32_t)(row_ * SA + lc * 8)) * 2;              \
            size_t goff_ = (size_t)ncl_ * HID + kb_ + lc * 8;                         \
            cpa16(sb + doff_ + (uint32_t)O_ASH * 2, Ah_ + goff_, sz_);                \
            cpa16(sb + doff_ + (uint32_t)O_ASL * 2, Al_ + goff_, sz_);                \
        }                                                                             \
        _Pragma("unroll")                                                             \
        for (int q_ = 0; q_ < 4; q_++) {                                              \
            int brow_ = lrow + q_ * 64;                                               \
            uint32_t bd_ = sb + (bs_ + O_BSH + (uint32_t)(brow_ * SA + lc * 8)) * 2;  \
            cpa16(bd_, Bh_ + (size_t)brow_ * HID + kb_ + lc * 8, 16);                 \
        }                                                                             \
    }

    LOAD_TILE(0);
    cpa_commit();

    for (int it = 0; it < nIter; it++) {
        cpa_wait0();              // load(it) complete (issued a full compute ago)
        __syncthreads();          // single barrier per iteration
        uint32_t bufb = (uint32_t)(it & 1) * BUF_H;
        uint32_t ash = sb + (bufb + O_ASH) * 2;
        uint32_t asl = sb + (bufb + O_ASL) * 2;
        uint32_t bsh = sb + (bufb + O_BSH) * 2;
        if (it + 1 < nIter) { LOAD_TILE(it + 1); cpa_commit(); }
#pragma unroll
        for (int kk = 0; kk < 4; kk++) {
            int kof = kk * 16;
            uint32_t bh[8][2];
#pragma unroll
            for (int p = 0; p < 4; p++) {
                int n = warpN * 64 + p * 16 + b_n_l;
                uint32_t off = (uint32_t)(n * SA + kof + b_k_l) * 2;
                uint32_t r[4];
                ldsm_x4(r, bsh + off);
                bh[2 * p][0] = r[0]; bh[2 * p][1] = r[1];
                bh[2 * p + 1][0] = r[2]; bh[2 * p + 1][1] = r[3];
            }
#pragma unroll
            for (int mt = 0; mt < 2; mt++) {
                int row = warpM * 32 + mt * 16 + a_row_l;
                uint32_t off = (uint32_t)(row * SA + kof + a_k_l) * 2;
                uint32_t ah[4], al[4];
                ldsm_x4(ah, ash + off);
                ldsm_x4(al, asl + off);
#pragma unroll
                for (int nt = 0; nt < 8; nt++) {
                    mma16816(acc[mt][nt], ah, bh[nt]);
                    mma16816(acc[mt][nt], al, bh[nt]);
                }
            }
        }
    }
    __syncthreads();

    // ---------------- epilogue ---------------------------------------------------
    int colb = warpN * 64 + tig * 2;
    if (mode == 0) {
#pragma unroll
        for (int mt = 0; mt < 2; mt++)
#pragma unroll
            for (int up = 0; up < 2; up++) {
                int rnode = mbase + warpM * 32 + mt * 16 + gid + up * 8;
                if (rnode < M) {
#pragma unroll
                    for (int nt = 0; nt < 8; nt++) {
                        int col = colb + nt * 8;
                        float2 v = make_float2(acc[mt][nt][up * 2] + fs[F_BIAS + col],
                                               acc[mt][nt][up * 2 + 1] + fs[F_BIAS + col + 1]);
                        *(float2*)(out1 + (size_t)rnode * HID + col) = v;
                    }
                }
            }
    } else if (mode == 1) {
#pragma unroll
        for (int mt = 0; mt < 2; mt++)
#pragma unroll
            for (int up = 0; up < 2; up++) {
                float s = 0.f, q = 0.f;
#pragma unroll
                for (int nt = 0; nt < 8; nt++) {
                    int col = colb + nt * 8;
                    float v0 = fmaxf(acc[mt][nt][up * 2] + fs[F_BIAS + col], 0.f);
                    float v1 = fmaxf(acc[mt][nt][up * 2 + 1] + fs[F_BIAS + col + 1], 0.f);
                    s += v0 + v1; q += v0 * v0 + v1 * v1;
                }
                s += __shfl_xor_sync(0xffffffffu, s, 1); q += __shfl_xor_sync(0xffffffffu, q, 1);
                s += __shfl_xor_sync(0xffffffffu, s, 2); q += __shfl_xor_sync(0xffffffffu, q, 2);
                if (tig == 0) {
                    int rl = warpM * 32 + mt * 16 + gid + up * 8;
                    fs[F_RS + rl * 4 + warpN] = s;
                    fs[F_RQ + rl * 4 + warpN] = q;
                }
            }
        __syncthreads();
        if (tid < 128) {
            float s = fs[F_RS + tid * 4] + fs[F_RS + tid * 4 + 1] +
                      fs[F_RS + tid * 4 + 2] + fs[F_RS + tid * 4 + 3];
            float q = fs[F_RQ + tid * 4] + fs[F_RQ + tid * 4 + 1] +
                      fs[F_RQ + tid * 4 + 2] + fs[F_RQ + tid * 4 + 3];
            float mean = s * (1.f / 256.f);
            float var = q * (1.f / 256.f) - mean * mean;
            fs[F_MEAN + tid] = mean;
            fs[F_RSTD + tid] = rsqrtf(fmaxf(var, 0.f) + 1e-5f);
        }
        __syncthreads();
#pragma unroll
        for (int mt = 0; mt < 2; mt++)
#pragma unroll
            for (int up = 0; up < 2; up++) {
                int rl = warpM * 32 + mt * 16 + gid + up * 8;
                int rnode = mbase + rl;
                if (rnode >= M) continue;
                float mean = fs[F_MEAN + rl], rstd = fs[F_RSTD + rl];
#pragma unroll
                for (int nt = 0; nt < 8; nt++) {
                    int col = colb + nt * 8;
                    float v0 = fmaxf(acc[mt][nt][up * 2] + fs[F_BIAS + col], 0.f);
                    float v1 = fmaxf(acc[mt][nt][up * 2 + 1] + fs[F_BIAS + col + 1], 0.f);
                    float o0 = (v0 - mean) * rstd * fs[F_LNG + col] + fs[F_LNB + col];
                    float o1 = (v1 - mean) * rstd * fs[F_LNG + col + 1] + fs[F_LNB + col + 1];
                    *(float2*)(out1 + (size_t)rnode * HID + col) = make_float2(o0, o1);
                    __half h0, h1, l0, l1;
                    split2(o0, &h0, &l0); split2(o1, &h1, &l1);
                    *(__half2*)(ohi + (size_t)rnode * HID + col) = __halves2half2(h0, h1);
                    *(__half2*)(olo + (size_t)rnode * HID + col) = __halves2half2(l0, l1);
                }
            }
    } else if (mode == 2) {
#pragma unroll
        for (int mt = 0; mt < 2; mt++)
#pragma unroll
            for (int up = 0; up < 2; up++) {
                int rnode = mbase + warpM * 32 + mt * 16 + gid + up * 8;
                if (rnode >= M) continue;
#pragma unroll
                for (int nt = 0; nt < 8; nt++) {
                    int col = colb + nt * 8;
                    float v0 = acc[mt][nt][up * 2] + fs[F_BIAS + col];
                    float v1 = acc[mt][nt][up * 2 + 1] + fs[F_BIAS + col + 1];
                    *(float2*)(out1 + (size_t)rnode * HID + col) = make_float2(v0, v1);
                    float r0 = fmaxf(v0, 0.f), r1 = fmaxf(v1, 0.f);
                    __half h0, h1, l0, l1;
                    split2(r0, &h0, &l0); split2(r1, &h1, &l1);
                    *(__half2*)(ohi + (size_t)rnode * HID + col) = __halves2half2(h0, h1);
                    *(__half2*)(olo + (size_t)rnode * HID + col) = __halves2half2(l0, l1);
                }
            }
    } else {  // mode 3: post-MLP head
#pragma unroll
        for (int mt = 0; mt < 2; mt++)
#pragma unroll
            for (int up = 0; up < 2; up++) {
                float p[5] = {0.f, 0.f, 0.f, 0.f, 0.f};
#pragma unroll
                for (int nt = 0; nt < 8; nt++) {
                    int col = colb + nt * 8;
                    float v0 = acc[mt][nt][up * 2] + fs[F_BIAS + col];
                    float v1 = acc[mt][nt][up * 2 + 1] + fs[F_BIAS + col + 1];
#pragma unroll
                    for (int o = 0; o < 5; o++)
                        p[o] += v0 * fs[F_W2 + o * 256 + col] + v1 * fs[F_W2 + o * 256 + col + 1];
                }
#pragma unroll
                for (int o = 0; o < 5; o++) {
                    p[o] += __shfl_xor_sync(0xffffffffu, p[o], 1);
                    p[o] += __shfl_xor_sync(0xffffffffu, p[o], 2);
                }
                if (tig == 0) {
                    int rl = warpM * 32 + mt * 16 + gid + up * 8;
#pragma unroll
                    for (int o = 0; o < 5; o++)
                        fs[F_HS + (rl * 4 + warpN) * 5 + o] = p[o];
                }
            }
        __syncthreads();
        if (tid < 128) {
            float l[5];
#pragma unroll
            for (int o = 0; o < 5; o++)
                l[o] = fs[F_HS + (tid * 4 + 0) * 5 + o] + fs[F_HS + (tid * 4 + 1) * 5 + o] +
                       fs[F_HS + (tid * 4 + 2) * 5 + o] + fs[F_HS + (tid * 4 + 3) * 5 + o] +
                       fs[F_B2 + o];
            float m = fmaxf(fmaxf(fmaxf(l[0], l[1]), fmaxf(l[2], l[3])), l[4]);
            float ssum = expf(l[0] - m) + expf(l[1] - m) + expf(l[2] - m) +
                         expf(l[3] - m) + expf(l[4] - m);
            float L = m + logf(ssum);
            int node = mbase + tid;
            if (node < M) {
                float* op = out1 + (size_t)node * 5;
#pragma unroll
                for (int o = 0; o < 5; o++) op[o] = l[o] - L;
            }
        }
    }
}

// ---------------- all-weight conversion (9 matrices, one launch) ---------------
__global__ void convert_all_kernel(const float* __restrict__ w_self,
                                   const float* __restrict__ w_lin,
                                   const float* __restrict__ sage_wl,
                                   const float* __restrict__ sage_wr,
                                   const float* __restrict__ post_w1) {
    int widx = blockIdx.x >> 8;
    int row = blockIdx.x & 255;
    int col = threadIdx.x;
    const size_t WS = (size_t)HID * HID;
    const float* src;
    int Kreal;
    if (widx == 0)      { src = w_self;  Kreal = LIN; }
    else if (widx == 1) { src = w_lin;   Kreal = LIN; }
    else if (widx <= 4) { src = sage_wl + (size_t)(widx - 2) * WS; Kreal = HID; }
    else if (widx <= 7) { src = sage_wr + (size_t)(widx - 5) * WS; Kreal = HID; }
    else                { src = post_w1; Kreal = HID; }
    float v = (col < Kreal) ? src[(size_t)row * Kreal + col] : 0.f;
    g_w_hi[(size_t)widx * WS + (size_t)row * HID + col] = __float2half_rn(v);
}

// ---------------- conv 3x3 VALID + bias + relu -> hi/lo fp16 -------------------
__global__ void conv_relu_kernel(const float* __restrict__ x,
                                 const float* __restrict__ w,
                                 const float* __restrict__ b) {
    __shared__ float xs[324];
    __shared__ float ws[144];
    __shared__ float bs[4];
    int n = blockIdx.x;
    int t = threadIdx.x;
    const float* xp = x + (size_t)n * 324;
    for (int i = t; i < 324; i += 256) xs[i] = xp[i];
    if (t < 144) ws[t] = w[t];
    if (t < 4)   bs[t] = b[t];
    __syncthreads();
    __half hi = __float2half_rn(0.f), lo = hi;
    if (t < LIN) {
        int co = t / 49, r = t % 49, oi = r / 7, oj = r % 7;
        float s = bs[co];
#pragma unroll
        for (int ci = 0; ci < 4; ci++)
#pragma unroll
            for (int ki = 0; ki < 3; ki++)
#pragma unroll
                for (int kj = 0; kj < 3; kj++)
                    s += xs[ci * 81 + (oi + ki) * 9 + (oj + kj)] *
                         ws[((co * 4 + ci) * 3 + ki) * 3 + kj];
        s = fmaxf(s, 0.f);
        split2(s, &hi, &lo);
    }
    g_h_hi[(size_t)n * HID + t] = hi;
    g_h_lo[(size_t)n * HID + t] = lo;
}

// ---------------- CSR build ----------------------------------------------------
__global__ void zero_cnt_kernel(int Nn) {
    int i = blockIdx.x * blockDim.x + threadIdx.x;
    if (i < Nn) g_cnt[i] = 0;
}
__global__ void hist_kernel(const int* __restrict__ ei, int E) {
    int e = blockIdx.x * blockDim.x + threadIdx.x;
    if (e < E) atomicAdd(&g_cnt[ei[E + e]], 1);
}
__global__ void scan_kernel(int Nn) {
    __shared__ int sums[1024];
    int t = threadIdx.x;
    int chunk = (Nn + 1023) / 1024;
    int beg = t * chunk;
    int end = beg + chunk; if (end > Nn) end = Nn;
    int s = 0;
    for (int i = beg; i < end && i >= 0; i++) s += g_cnt[i];
    sums[t] = s;
    __syncthreads();
    for (int off = 1; off < 1024; off <<= 1) {
        int v = 0;
        if (t >= off) v = sums[t - off];
        __syncthreads();
        sums[t] += v;
        __syncthreads();
    }
    int run = sums[t] - s;
    for (int i = beg; i < end; i++) { g_rowptr[i] = run; run += g_cnt[i]; }
    if (t == 1023) g_rowptr[Nn] = sums[1023];
}
__global__ void cursor_invdeg_kernel(int Nn) {
    int i = blockIdx.x * blockDim.x + threadIdx.x;
    if (i < Nn) {
        int r0 = g_rowptr[i], r1 = g_rowptr[i + 1];
        g_cnt[i] = r0;
        int d = r1 - r0;
        g_invdeg[i] = d > 0 ? 1.0f / (float)d : 0.0f;
    }
}
__global__ void scatter_kernel(const int* __restrict__ ei, int E) {
    int e = blockIdx.x * blockDim.x + threadIdx.x;
    if (e < E) {
        int d = ei[E + e];
        int pos = atomicAdd(&g_cnt[d], 1);
        g_esrc[pos] = ei[e];
    }
}

// ---------------- aggregation (warp per node) -----------------------------------
__global__ void agg_first_kernel(const float* __restrict__ neigh,
                                 float* __restrict__ xcur, int Nn) {
    int gw = (blockIdx.x * blockDim.x + threadIdx.x) >> 5;
    if (gw >= Nn) return;
    int lane = threadIdx.x & 31;
    int beg = g_rowptr[gw], end = g_rowptr[gw + 1];
    float4 a0 = make_float4(0, 0, 0, 0), a1 = a0;
    for (int e = beg; e < end; e++) {
        int s = g_esrc[e];
        if (s == gw) continue;
        const float4* p = (const float4*)(neigh + (size_t)s * HID);
        float4 v0 = p[lane], v1 = p[lane + 32];
        a0.x += v0.x; a0.y += v0.y; a0.z += v0.z; a0.w += v0.w;
        a1.x += v1.x; a1.y += v1.y; a1.z += v1.z; a1.w += v1.w;
    }
    float4* q = (float4*)(xcur + (size_t)gw * HID);
    float4 c0 = q[lane], c1 = q[lane + 32];
    c0.x += a0.x; c0.y += a0.y; c0.z += a0.z; c0.w += a0.w;
    c1.x += a1.x; c1.y += a1.y; c1.z += a1.z; c1.w += a1.w;
    q[lane] = c0; q[lane + 32] = c1;
    __half2* hh = (__half2*)(g_xc_hi + (size_t)gw * HID);
    __half2* ll = (__half2*)(g_xc_lo + (size_t)gw * HID);
    split_store4(c0, hh + lane * 2, ll + lane * 2);
    split_store4(c1, hh + 64 + lane * 2, ll + 64 + lane * 2);
}
__global__ void agg_mean_kernel(const float* __restrict__ xcur, int Nn) {
    int gw = (blockIdx.x * blockDim.x + threadIdx.x) >> 5;
    if (gw >= Nn) return;
    int lane = threadIdx.x & 31;
    int beg = g_rowptr[gw], end = g_rowptr[gw + 1];
    float4 a0 = make_float4(0, 0, 0, 0), a1 = a0;
    for (int e = beg; e < end; e++) {
        int s = g_esrc[e];
        const float4* p = (const float4*)(xcur + (size_t)s * HID);
        float4 v0 = p[lane], v1 = p[lane + 32];
        a0.x += v0.x; a0.y += v0.y; a0.z += v0.z; a0.w += v0.w;
        a1.x += v1.x; a1.y += v1.y; a1.z += v1.z; a1.w += v1.w;
    }
    float sc = g_invdeg[gw];
    a0.x *= sc; a0.y *= sc; a0.z *= sc; a0.w *= sc;
    a1.x *= sc; a1.y *= sc; a1.z *= sc; a1.w *= sc;
    __half2* hh = (__half2*)(g_ag_hi + (size_t)gw * HID);
    __half2* ll = (__half2*)(g_ag_lo + (size_t)gw * HID);
    split_store4(a0, hh + lane * 2, ll + lane * 2);
    split_store4(a1, hh + 64 + lane * 2, ll + 64 + lane * 2);
}

// ---------------- launch -------------------------------------------------------
extern "C" void kernel_launch(void* const* d_in, const int* in_sizes, int n_in,
                              void* d_out, int out_size) {
    const float* x       = (const float*)d_in[0];
    const int*   ei      = (const int*)d_in[1];
    const float* conv_w  = (const float*)d_in[2];
    const float* conv_b  = (const float*)d_in[3];
    const float* w_self  = (const float*)d_in[4];
    const float* b_self  = (const float*)d_in[5];
    const float* w_lin   = (const float*)d_in[6];
    const float* b_lin   = (const float*)d_in[7];
    const float* sage_wl = (const float*)d_in[8];
    const float* sage_bl = (const float*)d_in[9];
    const float* sage_wr = (const float*)d_in[10];
    const float* ln_g    = (const float*)d_in[11];
    const float* ln_b    = (const float*)d_in[12];
    const float* post_w1 = (const float*)d_in[13];
    const float* post_b1 = (const float*)d_in[14];
    const float* post_w2 = (const float*)d_in[15];
    const float* post_b2 = (const float*)d_in[16];

    int N = in_sizes[0] / 324;
    int E = in_sizes[1] / 2;

    float* outp = (float*)d_out;
    float* emb  = outp;
    float* logp = outp + (size_t)N * HID;

    float *xcur, *neigh;
    __half *h_hi, *h_lo, *xc_hi, *xc_lo, *ag_hi, *ag_lo, *w_hi;
    cudaGetSymbolAddress((void**)&xcur,  g_xcur);
    cudaGetSymbolAddress((void**)&neigh, g_neigh);
    cudaGetSymbolAddress((void**)&h_hi,  g_h_hi);
    cudaGetSymbolAddress((void**)&h_lo,  g_h_lo);
    cudaGetSymbolAddress((void**)&xc_hi, g_xc_hi);
    cudaGetSymbolAddress((void**)&xc_lo, g_xc_lo);
    cudaGetSymbolAddress((void**)&ag_hi, g_ag_hi);
    cudaGetSymbolAddress((void**)&ag_lo, g_ag_lo);
    cudaGetSymbolAddress((void**)&w_hi,  g_w_hi);

    cudaFuncSetAttribute(mma_gemm,
                         cudaFuncAttributeMaxDynamicSharedMemorySize, SMEM_BYTES);

    const size_t WS = (size_t)HID * HID;
    int gTiles = (N + BM - 1) / BM;

    // #1: weight conversion
    convert_all_kernel<<<9 * 256, 256>>>(w_self, w_lin, sage_wl, sage_wr, post_w1);
    // #2: conv + relu -> h hi/lo
    conv_relu_kernel<<<N, 256>>>(x, conv_w, conv_b);
    // #3: zero histogram
    zero_cnt_kernel<<<(N + 255) / 256, 256>>>(N);
    // #4: GEMM: self_x -> xcur f32
    mma_gemm<<<gTiles, 512, SMEM_BYTES>>>(h_hi, h_lo, w_hi + 0 * WS,
                                          nullptr, nullptr, nullptr,
                                          b_self, N, 4, 0, xcur, nullptr, nullptr,
                                          nullptr, nullptr, nullptr, nullptr);
    // #5: histogram
    hist_kernel<<<(E + 255) / 256, 256>>>(ei, E);
    // #6: GEMM: neigh -> f32
    mma_gemm<<<gTiles, 512, SMEM_BYTES>>>(h_hi, h_lo, w_hi + 1 * WS,
                                          nullptr, nullptr, nullptr,
                                          b_lin, N, 4, 0, neigh, nullptr, nullptr,
                                          nullptr, nullptr, nullptr, nullptr);
    // #7-#9: CSR scan + cursors + scatter
    scan_kernel<<<1, 1024>>>(N);
    cursor_invdeg_kernel<<<(N + 255) / 256, 256>>>(N);
    scatter_kernel<<<(E + 255) / 256, 256>>>(ei, E);

    // #10: first-layer scatter-add -> xcur f32 + xc hi/lo
    int aggBlocks = (N + 7) / 8;
    agg_first_kernel<<<aggBlocks, 256>>>(neigh, xcur, N);

    // SAGE x3
    for (int i = 0; i < 3; i++) {
        agg_mean_kernel<<<aggBlocks, 256>>>(xcur, N);
        const __half* wlh = w_hi + (size_t)(2 + i) * WS;
        const __half* wrh = w_hi + (size_t)(5 + i) * WS;
        const float* bl = sage_bl + (size_t)i * HID;
        if (i < 2) {
            mma_gemm<<<gTiles, 512, SMEM_BYTES>>>(ag_hi, ag_lo, wlh,
                                                  xc_hi, xc_lo, wrh,
                                                  bl, N, 4, 1, xcur, xc_hi, xc_lo,
                                                  ln_g + (size_t)i * HID,
                                                  ln_b + (size_t)i * HID,
                                                  nullptr, nullptr);
        } else {
            mma_gemm<<<gTiles, 512, SMEM_BYTES>>>(ag_hi, ag_lo, wlh,
                                                  xc_hi, xc_lo, wrh,
                                                  bl, N, 4, 2, emb, xc_hi, xc_lo,
                                                  nullptr, nullptr, nullptr, nullptr);
        }
    }

    // post-MLP + head fused
    mma_gemm<<<gTiles, 512, SMEM_BYTES>>>(xc_hi, xc_lo, w_hi + 8 * WS,
                                          nullptr, nullptr, nullptr,
                                          post_b1, N, 4, 3, logp, nullptr, nullptr,
                                          nullptr, nullptr, post_w2, post_b2);
}